// round 5
// baseline (speedup 1.0000x reference)
#include <cuda_runtime.h>
#include <math.h>

// Problem constants (fixed by the reference)
#define NN 100000     // nodes
#define EE 1600000    // edges
#define FI 32         // input features
#define HH 16         // hidden
#define CC 10         // classes
#define CP 12         // padded classes (float4-friendly row stride)

// ---------------- device scratch (static; no allocation allowed) -------------
__device__ int   g_is64;
__device__ int   g_src[EE];
__device__ int   g_dst[EE];
__device__ float g_v[EE];

__device__ __align__(16) float g_Y0[NN * HH];   // x @ W1[0]
__device__ __align__(16) float g_Yd[NN * HH];   // x @ (W1[1]-W1[0])
__device__ __align__(16) float g_R1[NN * HH];   // x @ root1 + b1
__device__ __align__(16) float g_agg1[NN * HH];

__device__ __align__(16) float g_Z0[NN * CP];
__device__ __align__(16) float g_Zd[NN * CP];
__device__ __align__(16) float g_R2[NN * CP];
__device__ __align__(16) float g_agg2[NN * CP];

__device__ float g_deg[NN];

// ---------------- dtype detect: int64 vs int32 edge_index --------------------
// If edge_index is int64, the int32 view has every odd word == 0 (indices <
// 2^17, little-endian). If int32, odd words are random node ids.
__global__ void k_detect(const int* __restrict__ ei32) {
    __shared__ int s_any;
    if (threadIdx.x == 0) s_any = 0;
    __syncthreads();
    int v = 0;
    for (int i = 2 * threadIdx.x + 1; i < 4096; i += 2 * blockDim.x) v |= ei32[i];
    if (v) atomicOr(&s_any, 1);
    __syncthreads();
    if (threadIdx.x == 0) g_is64 = (s_any == 0) ? 1 : 0;
}

// ---------------- edge prep: normalize indices to int32, copy v --------------
__global__ void k_prep(const void* __restrict__ ei, const float* __restrict__ attr) {
    int e = blockIdx.x * blockDim.x + threadIdx.x;
    if (e >= EE) return;
    int s, d;
    if (g_is64) {
        const long long* p = (const long long*)ei;
        s = (int)p[e];
        d = (int)p[EE + e];
    } else {
        const int* p = (const int*)ei;
        s = p[e];
        d = p[EE + e];
    }
    g_src[e] = s;
    g_dst[e] = d;
    g_v[e]   = attr[e];   // K=2 -> v = attr * (K-1) = attr
}

// ---------------- layer-1 node precompute + zero accumulators ----------------
__global__ void k_node1(const float* __restrict__ x, const float* __restrict__ W1,
                        const float* __restrict__ root1, const float* __restrict__ b1) {
    __shared__ float sW0[FI * HH], sWd[FI * HH], sR[FI * HH], sB[HH];
    for (int i = threadIdx.x; i < FI * HH; i += blockDim.x) {
        float w0 = W1[i];
        sW0[i] = w0;
        sWd[i] = W1[FI * HH + i] - w0;
        sR[i]  = root1[i];
    }
    if (threadIdx.x < HH) sB[threadIdx.x] = b1[threadIdx.x];
    __syncthreads();

    int n = blockIdx.x * blockDim.x + threadIdx.x;
    if (n >= NN) return;

    float xr[FI];
    const float4* xp = (const float4*)(x + (size_t)n * FI);
#pragma unroll
    for (int i = 0; i < FI / 4; i++) {
        float4 t = xp[i];
        xr[4 * i + 0] = t.x; xr[4 * i + 1] = t.y;
        xr[4 * i + 2] = t.z; xr[4 * i + 3] = t.w;
    }

    float4 y0[4], yd[4], r1[4];
#pragma unroll
    for (int j = 0; j < 4; j++) {
        y0[j] = make_float4(0.f, 0.f, 0.f, 0.f);
        yd[j] = make_float4(0.f, 0.f, 0.f, 0.f);
        r1[j] = ((const float4*)sB)[j];
    }
#pragma unroll
    for (int i = 0; i < FI; i++) {
        float xi = xr[i];
        const float4* w0 = (const float4*)(sW0 + i * HH);
        const float4* wd = (const float4*)(sWd + i * HH);
        const float4* wr = (const float4*)(sR + i * HH);
#pragma unroll
        for (int j = 0; j < 4; j++) {
            float4 a = w0[j], b = wd[j], c = wr[j];
            y0[j].x = fmaf(xi, a.x, y0[j].x); y0[j].y = fmaf(xi, a.y, y0[j].y);
            y0[j].z = fmaf(xi, a.z, y0[j].z); y0[j].w = fmaf(xi, a.w, y0[j].w);
            yd[j].x = fmaf(xi, b.x, yd[j].x); yd[j].y = fmaf(xi, b.y, yd[j].y);
            yd[j].z = fmaf(xi, b.z, yd[j].z); yd[j].w = fmaf(xi, b.w, yd[j].w);
            r1[j].x = fmaf(xi, c.x, r1[j].x); r1[j].y = fmaf(xi, c.y, r1[j].y);
            r1[j].z = fmaf(xi, c.z, r1[j].z); r1[j].w = fmaf(xi, c.w, r1[j].w);
        }
    }
    float4* o0 = (float4*)(g_Y0 + (size_t)n * HH);
    float4* od = (float4*)(g_Yd + (size_t)n * HH);
    float4* orr = (float4*)(g_R1 + (size_t)n * HH);
    float4* a1 = (float4*)(g_agg1 + (size_t)n * HH);
    float4* a2 = (float4*)(g_agg2 + (size_t)n * CP);
    float4 z = make_float4(0.f, 0.f, 0.f, 0.f);
#pragma unroll
    for (int j = 0; j < 4; j++) { o0[j] = y0[j]; od[j] = yd[j]; orr[j] = r1[j]; a1[j] = z; }
    a2[0] = z; a2[1] = z; a2[2] = z;
    g_deg[n] = 0.f;
}

// ---------------- layer-1 edge scatter ---------------------------------------
__global__ void k_edge1() {
    int e = blockIdx.x * blockDim.x + threadIdx.x;
    if (e >= EE) return;
    int s = g_src[e], d = g_dst[e];
    float v = g_v[e];
    const float4* y0 = (const float4*)(g_Y0 + (size_t)s * HH);
    const float4* yd = (const float4*)(g_Yd + (size_t)s * HH);
    float4* a = (float4*)(g_agg1 + (size_t)d * HH);
#pragma unroll
    for (int j = 0; j < 4; j++) {
        float4 p = y0[j], q = yd[j];
        float4 m = make_float4(fmaf(v, q.x, p.x), fmaf(v, q.y, p.y),
                               fmaf(v, q.z, p.z), fmaf(v, q.w, p.w));
        atomicAdd(&a[j], m);   // sm_90+: red.global.v4.f32
    }
    atomicAdd(&g_deg[d], 1.0f);
}

// ---------------- layer-2 node: ELU + per-node precompute ---------------------
__global__ void k_node2(const float* __restrict__ W2, const float* __restrict__ root2,
                        const float* __restrict__ b2) {
    __shared__ float sZ0[HH * CP], sZd[HH * CP], sR[HH * CP], sB[CP];
    for (int idx = threadIdx.x; idx < HH * CP; idx += blockDim.x) {
        int i = idx / CP, c = idx % CP;
        float w0 = (c < CC) ? W2[i * CC + c] : 0.f;
        float w1 = (c < CC) ? W2[HH * CC + i * CC + c] : 0.f;
        sZ0[idx] = w0;
        sZd[idx] = w1 - w0;
        sR[idx]  = (c < CC) ? root2[i * CC + c] : 0.f;
    }
    if (threadIdx.x < CP) sB[threadIdx.x] = (threadIdx.x < CC) ? b2[threadIdx.x] : 0.f;
    __syncthreads();

    int n = blockIdx.x * blockDim.x + threadIdx.x;
    if (n >= NN) return;

    float rdeg = 1.0f / fmaxf(g_deg[n], 1.0f);
    const float4* ag = (const float4*)(g_agg1 + (size_t)n * HH);
    const float4* rr = (const float4*)(g_R1 + (size_t)n * HH);
    float h[HH];
#pragma unroll
    for (int j = 0; j < 4; j++) {
        float4 a = ag[j], r = rr[j];
        float t;
        t = fmaf(a.x, rdeg, r.x); h[4 * j + 0] = (t > 0.f) ? t : expm1f(t);
        t = fmaf(a.y, rdeg, r.y); h[4 * j + 1] = (t > 0.f) ? t : expm1f(t);
        t = fmaf(a.z, rdeg, r.z); h[4 * j + 2] = (t > 0.f) ? t : expm1f(t);
        t = fmaf(a.w, rdeg, r.w); h[4 * j + 3] = (t > 0.f) ? t : expm1f(t);
    }

    float4 z0[3], zd[3], r2[3];
#pragma unroll
    for (int j = 0; j < 3; j++) {
        z0[j] = make_float4(0.f, 0.f, 0.f, 0.f);
        zd[j] = make_float4(0.f, 0.f, 0.f, 0.f);
        r2[j] = ((const float4*)sB)[j];
    }
#pragma unroll
    for (int i = 0; i < HH; i++) {
        float hi = h[i];
        const float4* a = (const float4*)(sZ0 + i * CP);
        const float4* b = (const float4*)(sZd + i * CP);
        const float4* c = (const float4*)(sR + i * CP);
#pragma unroll
        for (int j = 0; j < 3; j++) {
            float4 wa = a[j], wb = b[j], wc = c[j];
            z0[j].x = fmaf(hi, wa.x, z0[j].x); z0[j].y = fmaf(hi, wa.y, z0[j].y);
            z0[j].z = fmaf(hi, wa.z, z0[j].z); z0[j].w = fmaf(hi, wa.w, z0[j].w);
            zd[j].x = fmaf(hi, wb.x, zd[j].x); zd[j].y = fmaf(hi, wb.y, zd[j].y);
            zd[j].z = fmaf(hi, wb.z, zd[j].z); zd[j].w = fmaf(hi, wb.w, zd[j].w);
            r2[j].x = fmaf(hi, wc.x, r2[j].x); r2[j].y = fmaf(hi, wc.y, r2[j].y);
            r2[j].z = fmaf(hi, wc.z, r2[j].z); r2[j].w = fmaf(hi, wc.w, r2[j].w);
        }
    }
    float4* o0 = (float4*)(g_Z0 + (size_t)n * CP);
    float4* od = (float4*)(g_Zd + (size_t)n * CP);
    float4* orr = (float4*)(g_R2 + (size_t)n * CP);
#pragma unroll
    for (int j = 0; j < 3; j++) { o0[j] = z0[j]; od[j] = zd[j]; orr[j] = r2[j]; }
}

// ---------------- layer-2 edge scatter ---------------------------------------
__global__ void k_edge2() {
    int e = blockIdx.x * blockDim.x + threadIdx.x;
    if (e >= EE) return;
    int s = g_src[e], d = g_dst[e];
    float v = g_v[e];
    const float4* z0 = (const float4*)(g_Z0 + (size_t)s * CP);
    const float4* zd = (const float4*)(g_Zd + (size_t)s * CP);
    float4* a = (float4*)(g_agg2 + (size_t)d * CP);
#pragma unroll
    for (int j = 0; j < 3; j++) {
        float4 p = z0[j], q = zd[j];
        float4 m = make_float4(fmaf(v, q.x, p.x), fmaf(v, q.y, p.y),
                               fmaf(v, q.z, p.z), fmaf(v, q.w, p.w));
        atomicAdd(&a[j], m);
    }
}

// ---------------- output: mean + root + log_softmax ---------------------------
__global__ void k_out(float* __restrict__ out) {
    int n = blockIdx.x * blockDim.x + threadIdx.x;
    if (n >= NN) return;
    float rdeg = 1.0f / fmaxf(g_deg[n], 1.0f);
    const float4* ag = (const float4*)(g_agg2 + (size_t)n * CP);
    const float4* rr = (const float4*)(g_R2 + (size_t)n * CP);
    float u[CP];
#pragma unroll
    for (int j = 0; j < 3; j++) {
        float4 a = ag[j], r = rr[j];
        u[4 * j + 0] = fmaf(a.x, rdeg, r.x);
        u[4 * j + 1] = fmaf(a.y, rdeg, r.y);
        u[4 * j + 2] = fmaf(a.z, rdeg, r.z);
        u[4 * j + 3] = fmaf(a.w, rdeg, r.w);
    }
    float m = u[0];
#pragma unroll
    for (int c = 1; c < CC; c++) m = fmaxf(m, u[c]);
    float s = 0.f;
#pragma unroll
    for (int c = 0; c < CC; c++) s += __expf(u[c] - m);
    float lse = m + logf(s);
    float* o = out + (size_t)n * CC;
#pragma unroll
    for (int c = 0; c < CC; c++) o[c] = u[c] - lse;
}

// ---------------- launch ------------------------------------------------------
extern "C" void kernel_launch(void* const* d_in, const int* in_sizes, int n_in,
                              void* d_out, int out_size) {
    const float* x     = (const float*)d_in[0];
    const void*  ei    = d_in[1];
    const float* attr  = (const float*)d_in[2];
    const float* W1    = (const float*)d_in[3];
    const float* root1 = (const float*)d_in[4];
    const float* b1    = (const float*)d_in[5];
    const float* W2    = (const float*)d_in[6];
    const float* root2 = (const float*)d_in[7];
    const float* b2    = (const float*)d_in[8];
    float* out = (float*)d_out;

    k_detect<<<1, 256>>>((const int*)ei);
    k_prep<<<(EE + 255) / 256, 256>>>(ei, attr);
    k_node1<<<(NN + 127) / 128, 128>>>(x, W1, root1, b1);
    k_edge1<<<(EE + 255) / 256, 256>>>();
    k_node2<<<(NN + 127) / 128, 128>>>(W2, root2, b2);
    k_edge2<<<(EE + 255) / 256, 256>>>();
    k_out<<<(NN + 127) / 128, 128>>>(out);
}